// round 7
// baseline (speedup 1.0000x reference)
#include <cuda_runtime.h>
#include <cuda_bf16.h>
#include <cstdint>

// Problem constants (fixed for this dataset)
#define B_   64
#define D_   256
#define HW_  1024            // 32*32
#define K_   1024            // num embeddings
#define NPIX (B_ * HW_)      // 65536
#define NELM (B_ * D_ * HW_) // 16777216
#define CAND_CAP 1048576
#define EPS_MARGIN 5e-3f
#define STAGE_CAP 3072

// ---------------------------------------------------------------------------
// Scratch (device globals; no cudaMalloc allowed)
// ---------------------------------------------------------------------------
__device__ unsigned long long g_best[NPIX];   // packed (orderable_score<<32)|k
__device__ float g_cn[K_];                    // |c_k|^2 (exact sequential chain)
__device__ float g_A[NPIX];                   // |x_n|^2 (exact sequential chain)
__device__ float g_part[B_ * D_];             // loss partials
__device__ float g_Xt[NPIX * D_];             // X transposed: [pix][d] fp32
__device__ __nv_bfloat16 g_Xt_bf[NPIX * D_];  // bf16 copy
__device__ __nv_bfloat16 g_Cbf[K_ * D_];      // codebook bf16
__device__ unsigned long long g_cand[CAND_CAP]; // (f32score_bits<<32)|(pix<<10)|k
__device__ unsigned int g_ncand;

__device__ __forceinline__ unsigned int float_to_ordered(float f) {
    unsigned int u = __float_as_uint(f);
    return (u & 0x80000000u) ? ~u : (u | 0x80000000u);
}
__device__ __forceinline__ float ordered_to_float(unsigned int o) {
    unsigned int u = (o & 0x80000000u) ? (o & 0x7FFFFFFFu) : ~o;
    return __uint_as_float(u);
}

__device__ __forceinline__ uint32_t smem_u32(const void* p) {
    uint32_t a;
    asm("{ .reg .u64 t; cvta.to.shared.u64 t, %1; cvt.u32.u64 %0, t; }"
        : "=r"(a) : "l"(p));
    return a;
}

// cp.async 16B (sm_80+, legal on plain sm_103 target)
__device__ __forceinline__ void cp16(uint32_t saddr, const void* g) {
    asm volatile("cp.async.cg.shared.global [%0], [%1], 16;"
                 :: "r"(saddr), "l"(g) : "memory");
}

// ldmatrix x4 (non-transposed, b16)
__device__ __forceinline__ void ldm_x4(uint32_t* r, uint32_t addr) {
    asm volatile("ldmatrix.sync.aligned.m8n8.x4.shared.b16 {%0,%1,%2,%3}, [%4];"
                 : "=r"(r[0]), "=r"(r[1]), "=r"(r[2]), "=r"(r[3]) : "r"(addr));
}

// bf16 HMMA m16n8k16, f32 accumulate (sm_80+)
__device__ __forceinline__ void mma_bf16(float* c, const uint32_t* a,
                                         uint32_t b0, uint32_t b1) {
    asm volatile(
        "mma.sync.aligned.m16n8k16.row.col.f32.bf16.bf16.f32 "
        "{%0,%1,%2,%3}, {%4,%5,%6,%7}, {%8,%9}, {%0,%1,%2,%3};"
        : "+f"(c[0]), "+f"(c[1]), "+f"(c[2]), "+f"(c[3])
        : "r"(a[0]), "r"(a[1]), "r"(a[2]), "r"(a[3]), "r"(b0), "r"(b1));
}

// ---------------------------------------------------------------------------
// Kernel 1: |c_k|^2 (exact sequential chain) FUSED with bf16 codebook convert
// + g_ncand reset. One thread per code row.
// ---------------------------------------------------------------------------
__global__ void cn_cbf_kernel(const float* __restrict__ C) {
    int k = blockIdx.x * blockDim.x + threadIdx.x;
    if (k == 0) g_ncand = 0;
    if (k >= K_) return;
    const float* row = C + (size_t)k * D_;
    __nv_bfloat16* brow = g_Cbf + (size_t)k * D_;
    float s = 0.f;
    for (int d = 0; d < D_; d++) {
        float v = row[d];
        brow[d] = __float2bfloat16(v);
        s = __fadd_rn(s, __fmul_rn(v, v));
    }
    g_cn[k] = s;
}

// ---------------------------------------------------------------------------
// Kernel 2: |x_p|^2 (exact sequential chain) FUSED with g_best init.
// Grid is exactly NPIX threads.
// ---------------------------------------------------------------------------
__global__ __launch_bounds__(1024)
void a_init_kernel(const float* __restrict__ X) {
    const int b = blockIdx.x;
    const int p = threadIdx.x;
    g_best[b * HW_ + p] = 0xFFFFFFFFFFFFFFFFull;
    const float* Xb = X + (size_t)b * D_ * HW_ + p;
    float s = 0.f;
    #pragma unroll 8
    for (int d = 0; d < D_; d++) {
        float v = Xb[(size_t)d * HW_];
        s = __fadd_rn(s, __fmul_rn(v, v));
    }
    g_A[b * HW_ + p] = s;
}

// ---------------------------------------------------------------------------
// Kernel 3: transpose X NCHW [b][d][p] -> pixel-major [pix][d], f32+bf16
// ---------------------------------------------------------------------------
__global__ __launch_bounds__(256)
void transpose_kernel(const float* __restrict__ X) {
    __shared__ float t[32][33];
    const int b  = blockIdx.z;
    const int dB = blockIdx.y * 32;
    const int pB = blockIdx.x * 32;
    const int tx = threadIdx.x;       // 0..31
    const int ty = threadIdx.y;       // 0..7

    const float* src = X + ((size_t)b * D_ + dB) * HW_ + pB;
    #pragma unroll
    for (int i = 0; i < 32; i += 8)
        t[ty + i][tx] = src[(size_t)(ty + i) * HW_ + tx];
    __syncthreads();

    const size_t obase = ((size_t)(b * HW_ + pB)) * D_ + dB;
    #pragma unroll
    for (int i = 0; i < 32; i += 8) {
        int row = ty + i;
        float v = t[tx][row];
        g_Xt[obase + (size_t)row * D_ + tx] = v;
        g_Xt_bf[obase + (size_t)row * D_ + tx] = __float2bfloat16(v);
    }
}

// ---------------------------------------------------------------------------
// Kernel 4: persistent-A bf16 HMMA GEMM. One CTA = 128 pixels x ALL 1024 codes.
// 512 threads / 16 warps, warp tile 32x32 (2x latency hiding vs 64x32), scores
// written IN PLACE over the accumulators (no extra register array).
// A staged once; B double-buffered via cp.async. Running per-pixel min in smem;
// emission vs running min (superset), final flush re-filters vs final min.
// ---------------------------------------------------------------------------
__global__ __launch_bounds__(512, 1)
void vq_mma_kernel() {
    extern __shared__ char dsm_raw[];
    __shared__ float s_cn[K_];
    __shared__ unsigned int s_min[128];
    __shared__ unsigned long long stage[STAGE_CAP];
    __shared__ unsigned int s_cnt;

    const int tid = threadIdx.x, lane = tid & 31, wid = tid >> 5;
    const int pt = blockIdx.x;   // 0..511 pixel tiles (128 pixels each)

    const uint32_t s0 = smem_u32(dsm_raw);
    const uint32_t base = (s0 + 1023) & ~1023u;
    const uint32_t sA = base;
    const uint32_t sB0 = base + 65536, sB1 = base + 131072;

    #pragma unroll
    for (int i = 0; i < 2; i++) s_cn[tid + i * 512] = g_cn[tid + i * 512];
    if (tid < 128) s_min[tid] = 0xFFFFFFFFu;
    if (tid == 0) s_cnt = 0;

    // Stage A (once) + B tile 0
    const __nv_bfloat16* gA = g_Xt_bf + (size_t)pt * 128 * D_;
    #pragma unroll
    for (int i = 0; i < 8; i++) {
        int v = i * 512 + tid;             // 0..4095 16B chunks
        int r = v >> 5, c = v & 31;
        uint32_t off = (uint32_t)(r * 512) + (((uint32_t)c * 16) ^ ((uint32_t)(r & 7) << 4));
        cp16(sA + off, gA + (size_t)v * 8);
        cp16(sB0 + off, g_Cbf + (size_t)v * 8);
    }
    asm volatile("cp.async.commit_group;");

    // Warp tiling: 4 (m) x 4 (n), 32x32 per warp
    const int wm = (wid & 3) * 32;
    const int wn = (wid >> 2) * 32;
    const int a_row = wm + (lane & 15);
    const uint32_t a_swz = (uint32_t)((a_row & 7) << 4);
    const int a_kb = (lane >> 4) * 16;
    const int b_row = wn + ((lane & 7) | ((lane & 16) >> 1));
    const uint32_t b_swz = (uint32_t)((b_row & 7) << 4);
    const int b_kb = ((lane >> 3) & 1) * 16;

    const int r0b = wm + (lane >> 2);          // score row base (mi adds 16)
    const int c0b = wn + (lane & 3) * 2;       // score col base (nt adds 8)

    for (int kt = 0; kt < 8; kt++) {
        const uint32_t sBc = (kt & 1) ? sB1 : sB0;
        const uint32_t sBn = (kt & 1) ? sB0 : sB1;

        asm volatile("cp.async.wait_group 0;" ::: "memory");
        __syncthreads();

        // Prefetch next B tile into the alternate buffer
        if (kt + 1 < 8) {
            const __nv_bfloat16* gBn = g_Cbf + (size_t)(kt + 1) * 128 * D_;
            #pragma unroll
            for (int i = 0; i < 8; i++) {
                int v = i * 512 + tid;
                int r = v >> 5, c = v & 31;
                uint32_t off = (uint32_t)(r * 512) +
                               (((uint32_t)c * 16) ^ ((uint32_t)(r & 7) << 4));
                cp16(sBn + off, gBn + (size_t)v * 8);
            }
            asm volatile("cp.async.commit_group;");
        }

        float acc[2][4][4];
        #pragma unroll
        for (int mi = 0; mi < 2; mi++)
            #pragma unroll
            for (int nt = 0; nt < 4; nt++)
                #pragma unroll
                for (int e = 0; e < 4; e++) acc[mi][nt][e] = 0.f;

        #pragma unroll
        for (int ks = 0; ks < 16; ks++) {
            uint32_t af[2][4], bf[2][4];
            #pragma unroll
            for (int mi = 0; mi < 2; mi++)
                ldm_x4(af[mi], sA + (uint32_t)(a_row + mi * 16) * 512 +
                               (((uint32_t)(ks * 32 + a_kb)) ^ a_swz));
            #pragma unroll
            for (int nj = 0; nj < 2; nj++)
                ldm_x4(bf[nj], sBc + (uint32_t)(b_row + nj * 16) * 512 +
                               (((uint32_t)(ks * 32 + b_kb)) ^ b_swz));
            #pragma unroll
            for (int mi = 0; mi < 2; mi++)
                #pragma unroll
                for (int nt = 0; nt < 4; nt++)
                    mma_bf16(acc[mi][nt], af[mi],
                             bf[nt >> 1][(nt & 1) * 2], bf[nt >> 1][(nt & 1) * 2 + 1]);
        }

        // Scores IN PLACE: acc <- cn[k] - 2*acc. Update per-pixel running min.
        #pragma unroll
        for (int mi = 0; mi < 2; mi++) {
            float m0 = 3.4e38f, m1 = 3.4e38f;
            #pragma unroll
            for (int nt = 0; nt < 4; nt++) {
                int c0 = c0b + nt * 8;
                float cn0 = s_cn[kt * 128 + c0], cn1 = s_cn[kt * 128 + c0 + 1];
                acc[mi][nt][0] = fmaf(-2.f, acc[mi][nt][0], cn0);
                acc[mi][nt][1] = fmaf(-2.f, acc[mi][nt][1], cn1);
                acc[mi][nt][2] = fmaf(-2.f, acc[mi][nt][2], cn0);
                acc[mi][nt][3] = fmaf(-2.f, acc[mi][nt][3], cn1);
                m0 = fminf(m0, fminf(acc[mi][nt][0], acc[mi][nt][1]));
                m1 = fminf(m1, fminf(acc[mi][nt][2], acc[mi][nt][3]));
            }
            m0 = fminf(m0, __shfl_xor_sync(0xFFFFFFFFu, m0, 1));
            m0 = fminf(m0, __shfl_xor_sync(0xFFFFFFFFu, m0, 2));
            m1 = fminf(m1, __shfl_xor_sync(0xFFFFFFFFu, m1, 1));
            m1 = fminf(m1, __shfl_xor_sync(0xFFFFFFFFu, m1, 2));
            if ((lane & 3) == 0) {
                atomicMin(&s_min[r0b + mi * 16],     float_to_ordered(m0));
                atomicMin(&s_min[r0b + mi * 16 + 8], float_to_ordered(m1));
            }
        }
        __syncthreads();

        // Emit candidates vs running min (superset of final set)
        const unsigned pixb = (unsigned)(pt * 128);
        #pragma unroll
        for (int mi = 0; mi < 2; mi++) {
            int r0 = r0b + mi * 16;
            float thr0 = ordered_to_float(s_min[r0]) + EPS_MARGIN;
            float thr1 = ordered_to_float(s_min[r0 + 8]) + EPS_MARGIN;
            #pragma unroll
            for (int nt = 0; nt < 4; nt++) {
                int c0 = c0b + nt * 8;
                #pragma unroll
                for (int e = 0; e < 4; e++) {
                    float v = acc[mi][nt][e];
                    float thr = (e < 2) ? thr0 : thr1;
                    if (v <= thr) {
                        unsigned row = (unsigned)(r0 + ((e < 2) ? 0 : 8));
                        unsigned k = (unsigned)(kt * 128 + c0 + (e & 1));
                        unsigned long long entry =
                            ((unsigned long long)__float_as_uint(v) << 32) |
                            ((unsigned long long)(pixb + row) << 10) | k;
                        unsigned slot = atomicAdd(&s_cnt, 1u);
                        if (slot < STAGE_CAP) stage[slot] = entry;
                        else {
                            unsigned gs = atomicAdd(&g_ncand, 1u);
                            if (gs < CAND_CAP) g_cand[gs] = entry;
                        }
                    }
                }
            }
        }
    }
    __syncthreads();

    // Final flush: keep only entries within EPS of the FINAL per-pixel min
    const unsigned total = min(s_cnt, (unsigned)STAGE_CAP);
    const unsigned rounded = (total + 511u) & ~511u;
    for (unsigned i = tid; i < rounded; i += 512) {
        bool pred = false;
        unsigned long long e = 0;
        if (i < total) {
            e = stage[i];
            float v = __uint_as_float((unsigned)(e >> 32));
            unsigned row = ((unsigned)e >> 10) & 127u;
            pred = (v <= ordered_to_float(s_min[row]) + EPS_MARGIN);
        }
        unsigned mask = __ballot_sync(0xFFFFFFFFu, pred);
        if (mask) {
            int leader = __ffs(mask) - 1;
            unsigned bidx = 0;
            if (lane == leader) bidx = atomicAdd(&g_ncand, (unsigned)__popc(mask));
            bidx = __shfl_sync(0xFFFFFFFFu, bidx, leader);
            if (pred) {
                unsigned dst = bidx + __popc(mask & ((1u << lane) - 1u));
                if (dst < CAND_CAP) g_cand[dst] = e;
            }
        }
    }
}

// ---------------------------------------------------------------------------
// Kernel 5: exact fp32 rescore of candidates (one warp each).
// score = fl(fl(A - 2*dot) + cn)  — the Round-2-validated rounding chain.
// ---------------------------------------------------------------------------
__global__ __launch_bounds__(256)
void rescore_kernel(const float* __restrict__ C) {
    const unsigned int count = min(g_ncand, (unsigned)CAND_CAP);
    const int lane = threadIdx.x & 31;
    const unsigned gw = (blockIdx.x * blockDim.x + threadIdx.x) >> 5;
    const unsigned nw = (gridDim.x * blockDim.x) >> 5;

    for (unsigned i = gw; i < count; i += nw) {
        unsigned long long e = g_cand[i];
        unsigned low = (unsigned)e;
        unsigned pix = low >> 10, k = low & 1023u;

        const float4* xr = reinterpret_cast<const float4*>(g_Xt + (size_t)pix * D_);
        const float4* cr = reinterpret_cast<const float4*>(C + (size_t)k * D_);
        float dot = 0.f;
        #pragma unroll
        for (int t = 0; t < 2; t++) {
            float4 xv = xr[lane * 2 + t];
            float4 cv = cr[lane * 2 + t];
            dot = fmaf(xv.x, cv.x, dot);
            dot = fmaf(xv.y, cv.y, dot);
            dot = fmaf(xv.z, cv.z, dot);
            dot = fmaf(xv.w, cv.w, dot);
        }
        #pragma unroll
        for (int o = 16; o > 0; o >>= 1) dot += __shfl_down_sync(0xFFFFFFFFu, dot, o);
        if (lane == 0) {
            float sc = __fadd_rn(__fadd_rn(g_A[pix], __fmul_rn(-2.0f, dot)), g_cn[k]);
            unsigned long long key =
                ((unsigned long long)float_to_ordered(sc) << 32) | (unsigned long long)k;
            atomicMin(&g_best[pix], key);
        }
    }
}

// ---------------------------------------------------------------------------
// Kernel 6: gather output (NCHW) + per-block loss partial sums.
// ---------------------------------------------------------------------------
__global__ __launch_bounds__(256)
void gather_kernel(const float* __restrict__ X, const float* __restrict__ C,
                   float* __restrict__ out) {
    __shared__ float red[8];
    const int bd = blockIdx.x;
    const int b  = bd >> 8;
    const int d  = bd & 255;
    const int p  = threadIdx.x * 4;

    const unsigned long long* __restrict__ best = &g_best[b * HW_];
    const size_t base = ((size_t)b * D_ + d) * HW_ + p;

    float4 x = *reinterpret_cast<const float4*>(&X[base]);
    float q[4];
    #pragma unroll
    for (int j = 0; j < 4; j++) {
        int k = (int)(unsigned int)(best[p + j] & 0xFFFFFFFFull);
        q[j] = C[(size_t)k * D_ + d];
    }
    *reinterpret_cast<float4*>(&out[base]) = make_float4(q[0], q[1], q[2], q[3]);

    float dx0 = q[0] - x.x, dx1 = q[1] - x.y, dx2 = q[2] - x.z, dx3 = q[3] - x.w;
    float s = dx0 * dx0 + dx1 * dx1 + dx2 * dx2 + dx3 * dx3;
    #pragma unroll
    for (int o = 16; o > 0; o >>= 1) s += __shfl_down_sync(0xFFFFFFFFu, s, o);
    int warp = threadIdx.x >> 5;
    if ((threadIdx.x & 31) == 0) red[warp] = s;
    __syncthreads();
    if (threadIdx.x == 0) {
        float t = 0.f;
        #pragma unroll
        for (int w = 0; w < 8; w++) t += red[w];
        g_part[bd] = t;
    }
}

// ---------------------------------------------------------------------------
// Kernel 7: final loss reduction
// ---------------------------------------------------------------------------
__global__ void finalize_kernel(float* __restrict__ out, int loss_idx) {
    __shared__ double red[256];
    double s = 0.0;
    for (int i = threadIdx.x; i < B_ * D_; i += 256) s += (double)g_part[i];
    red[threadIdx.x] = s;
    __syncthreads();
    for (int o = 128; o > 0; o >>= 1) {
        if (threadIdx.x < o) red[threadIdx.x] += red[threadIdx.x + o];
        __syncthreads();
    }
    if (threadIdx.x == 0) {
        double mse = red[0] / (double)NELM;
        out[loss_idx] = (float)(1.25 * mse);
    }
}

// ---------------------------------------------------------------------------
extern "C" void kernel_launch(void* const* d_in, const int* in_sizes, int n_in,
                              void* d_out, int out_size) {
    const float* X = (const float*)d_in[0];   // [64,256,32,32] f32 NCHW
    const float* C = (const float*)d_in[1];   // [1024,256] f32
    float* out = (float*)d_out;

    static const int SMEM_BYTES = 196608 + 1024;   // A + 2xB (+ align slack)
    cudaFuncSetAttribute(vq_mma_kernel,
                         cudaFuncAttributeMaxDynamicSharedMemorySize, SMEM_BYTES);

    cn_cbf_kernel<<<K_ / 256, 256>>>(C);                           // launch 1
    a_init_kernel<<<B_, 1024>>>(X);                                // launch 2
    transpose_kernel<<<dim3(HW_ / 32, D_ / 32, B_), dim3(32, 8)>>>(X); // 3
    vq_mma_kernel<<<NPIX / 128, 512, SMEM_BYTES>>>();              // launch 4
    rescore_kernel<<<1024, 256>>>(C);                              // launch 5
    gather_kernel<<<B_ * D_, 256>>>(X, C, out);                    // launch 6
    if (out_size > NELM) {
        finalize_kernel<<<1, 256>>>(out, out_size - 1);            // launch 7
    }
}

// round 8
// speedup vs baseline: 1.3072x; 1.3072x over previous
#include <cuda_runtime.h>
#include <cuda_bf16.h>
#include <cstdint>

// Problem constants (fixed for this dataset)
#define B_   64
#define D_   256
#define HW_  1024            // 32*32
#define K_   1024            // num embeddings
#define NPIX (B_ * HW_)      // 65536
#define NELM (B_ * D_ * HW_) // 16777216
#define CAND_CAP 1048576
#define EPS_MARGIN 5e-3f
#define STAGE_CAP 2816

// ---------------------------------------------------------------------------
// Scratch (device globals; no cudaMalloc allowed)
// ---------------------------------------------------------------------------
__device__ unsigned long long g_best[NPIX];   // packed (orderable_score<<32)|k
__device__ float g_cn[K_];                    // |c_k|^2 (exact sequential chain)
__device__ float g_A[NPIX];                   // |x_n|^2 (exact sequential chain)
__device__ float g_part[B_ * D_];             // loss partials
__device__ float g_Xt[NPIX * D_];             // X transposed: [pix][d] fp32
__device__ __nv_bfloat16 g_Xt_bf[NPIX * D_];  // bf16 copy
__device__ __nv_bfloat16 g_Cbf[K_ * D_];      // codebook bf16
__device__ unsigned long long g_cand[CAND_CAP]; // (f32score_bits<<32)|(pix<<10)|k
__device__ unsigned int g_ncand;

__device__ __forceinline__ unsigned int float_to_ordered(float f) {
    unsigned int u = __float_as_uint(f);
    return (u & 0x80000000u) ? ~u : (u | 0x80000000u);
}
__device__ __forceinline__ float ordered_to_float(unsigned int o) {
    unsigned int u = (o & 0x80000000u) ? (o & 0x7FFFFFFFu) : ~o;
    return __uint_as_float(u);
}

__device__ __forceinline__ uint32_t smem_u32(const void* p) {
    uint32_t a;
    asm("{ .reg .u64 t; cvta.to.shared.u64 t, %1; cvt.u32.u64 %0, t; }"
        : "=r"(a) : "l"(p));
    return a;
}

// cp.async 16B (sm_80+, legal on plain sm_103 target)
__device__ __forceinline__ void cp16(uint32_t saddr, const void* g) {
    asm volatile("cp.async.cg.shared.global [%0], [%1], 16;"
                 :: "r"(saddr), "l"(g) : "memory");
}

// ldmatrix x4 (non-transposed, b16)
__device__ __forceinline__ void ldm_x4(uint32_t* r, uint32_t addr) {
    asm volatile("ldmatrix.sync.aligned.m8n8.x4.shared.b16 {%0,%1,%2,%3}, [%4];"
                 : "=r"(r[0]), "=r"(r[1]), "=r"(r[2]), "=r"(r[3]) : "r"(addr));
}

// bf16 HMMA m16n8k16, f32 accumulate (sm_80+)
__device__ __forceinline__ void mma_bf16(float* c, const uint32_t* a,
                                         uint32_t b0, uint32_t b1) {
    asm volatile(
        "mma.sync.aligned.m16n8k16.row.col.f32.bf16.bf16.f32 "
        "{%0,%1,%2,%3}, {%4,%5,%6,%7}, {%8,%9}, {%0,%1,%2,%3};"
        : "+f"(c[0]), "+f"(c[1]), "+f"(c[2]), "+f"(c[3])
        : "r"(a[0]), "r"(a[1]), "r"(a[2]), "r"(a[3]), "r"(b0), "r"(b1));
}

// ---------------------------------------------------------------------------
// Kernel 1: |c_k|^2 (exact sequential chain) + bf16 convert, COALESCED.
// 32 blocks x 256 threads. Rows staged in padded smem via float4 loads;
// 32 threads then run the sequential chains from smem (stride 257 = no
// bank conflicts). bf16 stores fused with the load phase (coalesced).
// ---------------------------------------------------------------------------
__global__ __launch_bounds__(256)
void cn_cbf_kernel(const float* __restrict__ C) {
    __shared__ float rows[32][257];
    const int tid = threadIdx.x;
    const int kb = blockIdx.x * 32;
    if (blockIdx.x == 0 && tid == 0) g_ncand = 0;

    const float4* C4 = reinterpret_cast<const float4*>(C + (size_t)kb * D_);
    uint2* B2 = reinterpret_cast<uint2*>(g_Cbf + (size_t)kb * D_);
    #pragma unroll
    for (int i = 0; i < 8; i++) {
        int idx = i * 256 + tid;          // float4 index: 0..2047
        int r = idx >> 6, c = idx & 63;   // 64 float4 per row
        float4 v = C4[idx];
        rows[r][c * 4 + 0] = v.x;
        rows[r][c * 4 + 1] = v.y;
        rows[r][c * 4 + 2] = v.z;
        rows[r][c * 4 + 3] = v.w;
        __nv_bfloat162 h01 = __floats2bfloat162_rn(v.x, v.y);
        __nv_bfloat162 h23 = __floats2bfloat162_rn(v.z, v.w);
        uint2 pk;
        pk.x = *reinterpret_cast<unsigned int*>(&h01);
        pk.y = *reinterpret_cast<unsigned int*>(&h23);
        B2[idx] = pk;
    }
    __syncthreads();
    if (tid < 32) {
        float s = 0.f;
        #pragma unroll 8
        for (int d = 0; d < D_; d++) {
            float v = rows[tid][d];
            s = __fadd_rn(s, __fmul_rn(v, v));
        }
        g_cn[kb + tid] = s;
    }
}

// ---------------------------------------------------------------------------
// Kernel 2: |x_p|^2 (exact sequential chain) FUSED with g_best init.
// 256 blocks x 256 threads (full-chip spread), coalesced strided loads.
// ---------------------------------------------------------------------------
__global__ __launch_bounds__(256)
void a_init_kernel(const float* __restrict__ X) {
    const int pix = blockIdx.x * 256 + threadIdx.x;
    g_best[pix] = 0xFFFFFFFFFFFFFFFFull;
    const int b = pix >> 10, p = pix & 1023;
    const float* Xb = X + (size_t)b * D_ * HW_ + p;
    float s = 0.f;
    #pragma unroll 8
    for (int d = 0; d < D_; d++) {
        float v = Xb[(size_t)d * HW_];
        s = __fadd_rn(s, __fmul_rn(v, v));
    }
    g_A[pix] = s;
}

// ---------------------------------------------------------------------------
// Kernel 3: transpose X NCHW [b][d][p] -> pixel-major [pix][d], f32+bf16
// ---------------------------------------------------------------------------
__global__ __launch_bounds__(256)
void transpose_kernel(const float* __restrict__ X) {
    __shared__ float t[32][33];
    const int b  = blockIdx.z;
    const int dB = blockIdx.y * 32;
    const int pB = blockIdx.x * 32;
    const int tx = threadIdx.x;       // 0..31
    const int ty = threadIdx.y;       // 0..7

    const float* src = X + ((size_t)b * D_ + dB) * HW_ + pB;
    #pragma unroll
    for (int i = 0; i < 32; i += 8)
        t[ty + i][tx] = src[(size_t)(ty + i) * HW_ + tx];
    __syncthreads();

    const size_t obase = ((size_t)(b * HW_ + pB)) * D_ + dB;
    #pragma unroll
    for (int i = 0; i < 32; i += 8) {
        int row = ty + i;
        float v = t[tx][row];
        g_Xt[obase + (size_t)row * D_ + tx] = v;
        g_Xt_bf[obase + (size_t)row * D_ + tx] = __float2bfloat16(v);
    }
}

// ---------------------------------------------------------------------------
// Kernel 4: persistent-A bf16 HMMA GEMM. One CTA = 128 pixels x ALL 1024 codes.
// 512 threads / 16 warps, 32x32 warp tile, scores in place over accumulators.
// ONE __syncthreads per k-tile (emission reads a possibly-stale running min —
// monotone decreasing, hence a provable candidate superset; final flush
// re-filters vs the final min). Final flush counts candidates per pixel:
// single-candidate pixels write g_best directly (no exact rescore needed —
// EPS >= 2*bf16err guarantees the true argmin is in the candidate set);
// multi-candidate pixels go to g_cand for exact rescoring.
// ---------------------------------------------------------------------------
__global__ __launch_bounds__(512, 1)
void vq_mma_kernel() {
    extern __shared__ char dsm_raw[];
    __shared__ float s_cn[K_];
    __shared__ unsigned int s_min[128];
    __shared__ unsigned int s_pcount[128];
    __shared__ unsigned long long stage[STAGE_CAP];
    __shared__ unsigned int s_cnt;

    const int tid = threadIdx.x, lane = tid & 31, wid = tid >> 5;
    const int pt = blockIdx.x;   // 0..511 pixel tiles (128 pixels each)

    const uint32_t s0 = smem_u32(dsm_raw);
    const uint32_t base = (s0 + 1023) & ~1023u;
    const uint32_t sA = base;
    const uint32_t sB0 = base + 65536, sB1 = base + 131072;

    #pragma unroll
    for (int i = 0; i < 2; i++) s_cn[tid + i * 512] = g_cn[tid + i * 512];
    if (tid < 128) { s_min[tid] = 0xFFFFFFFFu; s_pcount[tid] = 0u; }
    if (tid == 0) s_cnt = 0;

    // Stage A (once) + B tile 0
    const __nv_bfloat16* gA = g_Xt_bf + (size_t)pt * 128 * D_;
    #pragma unroll
    for (int i = 0; i < 8; i++) {
        int v = i * 512 + tid;             // 0..4095 16B chunks
        int r = v >> 5, c = v & 31;
        uint32_t off = (uint32_t)(r * 512) + (((uint32_t)c * 16) ^ ((uint32_t)(r & 7) << 4));
        cp16(sA + off, gA + (size_t)v * 8);
        cp16(sB0 + off, g_Cbf + (size_t)v * 8);
    }
    asm volatile("cp.async.commit_group;");

    // Warp tiling: 4 (m) x 4 (n), 32x32 per warp
    const int wm = (wid & 3) * 32;
    const int wn = (wid >> 2) * 32;
    const int a_row = wm + (lane & 15);
    const uint32_t a_swz = (uint32_t)((a_row & 7) << 4);
    const int a_kb = (lane >> 4) * 16;
    const int b_row = wn + ((lane & 7) | ((lane & 16) >> 1));
    const uint32_t b_swz = (uint32_t)((b_row & 7) << 4);
    const int b_kb = ((lane >> 3) & 1) * 16;

    const int r0b = wm + (lane >> 2);          // score row base (mi adds 16)
    const int c0b = wn + (lane & 3) * 2;       // score col base (nt adds 8)

    for (int kt = 0; kt < 8; kt++) {
        const uint32_t sBc = (kt & 1) ? sB1 : sB0;
        const uint32_t sBn = (kt & 1) ? sB0 : sB1;

        asm volatile("cp.async.wait_group 0;" ::: "memory");
        __syncthreads();

        // Prefetch next B tile into the alternate buffer
        if (kt + 1 < 8) {
            const __nv_bfloat16* gBn = g_Cbf + (size_t)(kt + 1) * 128 * D_;
            #pragma unroll
            for (int i = 0; i < 8; i++) {
                int v = i * 512 + tid;
                int r = v >> 5, c = v & 31;
                uint32_t off = (uint32_t)(r * 512) +
                               (((uint32_t)c * 16) ^ ((uint32_t)(r & 7) << 4));
                cp16(sBn + off, gBn + (size_t)v * 8);
            }
            asm volatile("cp.async.commit_group;");
        }

        float acc[2][4][4];
        #pragma unroll
        for (int mi = 0; mi < 2; mi++)
            #pragma unroll
            for (int nt = 0; nt < 4; nt++)
                #pragma unroll
                for (int e = 0; e < 4; e++) acc[mi][nt][e] = 0.f;

        #pragma unroll
        for (int ks = 0; ks < 16; ks++) {
            uint32_t af[2][4], bf[2][4];
            #pragma unroll
            for (int mi = 0; mi < 2; mi++)
                ldm_x4(af[mi], sA + (uint32_t)(a_row + mi * 16) * 512 +
                               (((uint32_t)(ks * 32 + a_kb)) ^ a_swz));
            #pragma unroll
            for (int nj = 0; nj < 2; nj++)
                ldm_x4(bf[nj], sBc + (uint32_t)(b_row + nj * 16) * 512 +
                               (((uint32_t)(ks * 32 + b_kb)) ^ b_swz));
            #pragma unroll
            for (int mi = 0; mi < 2; mi++)
                #pragma unroll
                for (int nt = 0; nt < 4; nt++)
                    mma_bf16(acc[mi][nt], af[mi],
                             bf[nt >> 1][(nt & 1) * 2], bf[nt >> 1][(nt & 1) * 2 + 1]);
        }

        // Scores IN PLACE: acc <- cn[k] - 2*acc. Update per-pixel running min.
        #pragma unroll
        for (int mi = 0; mi < 2; mi++) {
            float m0 = 3.4e38f, m1 = 3.4e38f;
            #pragma unroll
            for (int nt = 0; nt < 4; nt++) {
                int c0 = c0b + nt * 8;
                float cn0 = s_cn[kt * 128 + c0], cn1 = s_cn[kt * 128 + c0 + 1];
                acc[mi][nt][0] = fmaf(-2.f, acc[mi][nt][0], cn0);
                acc[mi][nt][1] = fmaf(-2.f, acc[mi][nt][1], cn1);
                acc[mi][nt][2] = fmaf(-2.f, acc[mi][nt][2], cn0);
                acc[mi][nt][3] = fmaf(-2.f, acc[mi][nt][3], cn1);
                m0 = fminf(m0, fminf(acc[mi][nt][0], acc[mi][nt][1]));
                m1 = fminf(m1, fminf(acc[mi][nt][2], acc[mi][nt][3]));
            }
            m0 = fminf(m0, __shfl_xor_sync(0xFFFFFFFFu, m0, 1));
            m0 = fminf(m0, __shfl_xor_sync(0xFFFFFFFFu, m0, 2));
            m1 = fminf(m1, __shfl_xor_sync(0xFFFFFFFFu, m1, 1));
            m1 = fminf(m1, __shfl_xor_sync(0xFFFFFFFFu, m1, 2));
            if ((lane & 3) == 0) {
                atomicMin(&s_min[r0b + mi * 16],     float_to_ordered(m0));
                atomicMin(&s_min[r0b + mi * 16 + 8], float_to_ordered(m1));
            }
        }
        // NO syncthreads: stale (larger) min still yields a candidate superset.

        // Emit candidates vs running min
        const unsigned pixb = (unsigned)(pt * 128);
        #pragma unroll
        for (int mi = 0; mi < 2; mi++) {
            int r0 = r0b + mi * 16;
            float thr0 = ordered_to_float(s_min[r0]) + EPS_MARGIN;
            float thr1 = ordered_to_float(s_min[r0 + 8]) + EPS_MARGIN;
            #pragma unroll
            for (int nt = 0; nt < 4; nt++) {
                int c0 = c0b + nt * 8;
                #pragma unroll
                for (int e = 0; e < 4; e++) {
                    float v = acc[mi][nt][e];
                    float thr = (e < 2) ? thr0 : thr1;
                    if (v <= thr) {
                        unsigned row = (unsigned)(r0 + ((e < 2) ? 0 : 8));
                        unsigned k = (unsigned)(kt * 128 + c0 + (e & 1));
                        unsigned long long entry =
                            ((unsigned long long)__float_as_uint(v) << 32) |
                            ((unsigned long long)(pixb + row) << 10) | k;
                        unsigned slot = atomicAdd(&s_cnt, 1u);
                        if (slot < STAGE_CAP) stage[slot] = entry;
                        else {
                            unsigned gs = atomicAdd(&g_ncand, 1u);
                            if (gs < CAND_CAP) g_cand[gs] = entry;
                        }
                    }
                }
            }
        }
    }
    __syncthreads();

    // Final flush, pass 1: count final-filtered candidates per pixel
    const unsigned total = min(s_cnt, (unsigned)STAGE_CAP);
    const bool oflow = (s_cnt > (unsigned)STAGE_CAP);
    for (unsigned i = tid; i < total; i += 512) {
        unsigned long long e = stage[i];
        float v = __uint_as_float((unsigned)(e >> 32));
        unsigned row = ((unsigned)e >> 10) & 127u;
        if (v <= ordered_to_float(s_min[row]) + EPS_MARGIN)
            atomicAdd(&s_pcount[row], 1u);
    }
    __syncthreads();

    // Pass 2: singles -> direct g_best write; multis -> g_cand
    const unsigned rounded = (total + 511u) & ~511u;
    for (unsigned i = tid; i < rounded; i += 512) {
        bool pred = false;
        unsigned long long e = 0;
        if (i < total) {
            e = stage[i];
            float v = __uint_as_float((unsigned)(e >> 32));
            unsigned low = (unsigned)e;
            unsigned row = (low >> 10) & 127u;
            if (v <= ordered_to_float(s_min[row]) + EPS_MARGIN) {
                if (s_pcount[row] == 1u && !oflow) {
                    unsigned pix = low >> 10, k = low & 1023u;
                    unsigned long long key =
                        ((unsigned long long)float_to_ordered(v) << 32) |
                        (unsigned long long)k;
                    atomicMin(&g_best[pix], key);
                } else {
                    pred = true;
                }
            }
        }
        unsigned mask = __ballot_sync(0xFFFFFFFFu, pred);
        if (mask) {
            int leader = __ffs(mask) - 1;
            unsigned bidx = 0;
            if (lane == leader) bidx = atomicAdd(&g_ncand, (unsigned)__popc(mask));
            bidx = __shfl_sync(0xFFFFFFFFu, bidx, leader);
            if (pred) {
                unsigned dst = bidx + __popc(mask & ((1u << lane) - 1u));
                if (dst < CAND_CAP) g_cand[dst] = e;
            }
        }
    }
}

// ---------------------------------------------------------------------------
// Kernel 5: exact fp32 rescore of multi-candidate entries (one warp each).
// score = fl(fl(A - 2*dot) + cn)  — the Round-2-validated rounding chain.
// ---------------------------------------------------------------------------
__global__ __launch_bounds__(256)
void rescore_kernel(const float* __restrict__ C) {
    const unsigned int count = min(g_ncand, (unsigned)CAND_CAP);
    const int lane = threadIdx.x & 31;
    const unsigned gw = (blockIdx.x * blockDim.x + threadIdx.x) >> 5;
    const unsigned nw = (gridDim.x * blockDim.x) >> 5;

    for (unsigned i = gw; i < count; i += nw) {
        unsigned long long e = g_cand[i];
        unsigned low = (unsigned)e;
        unsigned pix = low >> 10, k = low & 1023u;

        const float4* xr = reinterpret_cast<const float4*>(g_Xt + (size_t)pix * D_);
        const float4* cr = reinterpret_cast<const float4*>(C + (size_t)k * D_);
        float dot = 0.f;
        #pragma unroll
        for (int t = 0; t < 2; t++) {
            float4 xv = xr[lane * 2 + t];
            float4 cv = cr[lane * 2 + t];
            dot = fmaf(xv.x, cv.x, dot);
            dot = fmaf(xv.y, cv.y, dot);
            dot = fmaf(xv.z, cv.z, dot);
            dot = fmaf(xv.w, cv.w, dot);
        }
        #pragma unroll
        for (int o = 16; o > 0; o >>= 1) dot += __shfl_down_sync(0xFFFFFFFFu, dot, o);
        if (lane == 0) {
            float sc = __fadd_rn(__fadd_rn(g_A[pix], __fmul_rn(-2.0f, dot)), g_cn[k]);
            unsigned long long key =
                ((unsigned long long)float_to_ordered(sc) << 32) | (unsigned long long)k;
            atomicMin(&g_best[pix], key);
        }
    }
}

// ---------------------------------------------------------------------------
// Kernel 6: gather output (NCHW) + per-block loss partial sums.
// ---------------------------------------------------------------------------
__global__ __launch_bounds__(256)
void gather_kernel(const float* __restrict__ X, const float* __restrict__ C,
                   float* __restrict__ out) {
    __shared__ float red[8];
    const int bd = blockIdx.x;
    const int b  = bd >> 8;
    const int d  = bd & 255;
    const int p  = threadIdx.x * 4;

    const unsigned long long* __restrict__ best = &g_best[b * HW_];
    const size_t base = ((size_t)b * D_ + d) * HW_ + p;

    float4 x = *reinterpret_cast<const float4*>(&X[base]);
    float q[4];
    #pragma unroll
    for (int j = 0; j < 4; j++) {
        int k = (int)(unsigned int)(best[p + j] & 0xFFFFFFFFull);
        q[j] = C[(size_t)k * D_ + d];
    }
    *reinterpret_cast<float4*>(&out[base]) = make_float4(q[0], q[1], q[2], q[3]);

    float dx0 = q[0] - x.x, dx1 = q[1] - x.y, dx2 = q[2] - x.z, dx3 = q[3] - x.w;
    float s = dx0 * dx0 + dx1 * dx1 + dx2 * dx2 + dx3 * dx3;
    #pragma unroll
    for (int o = 16; o > 0; o >>= 1) s += __shfl_down_sync(0xFFFFFFFFu, s, o);
    int warp = threadIdx.x >> 5;
    if ((threadIdx.x & 31) == 0) red[warp] = s;
    __syncthreads();
    if (threadIdx.x == 0) {
        float t = 0.f;
        #pragma unroll
        for (int w = 0; w < 8; w++) t += red[w];
        g_part[bd] = t;
    }
}

// ---------------------------------------------------------------------------
// Kernel 7: final loss reduction
// ---------------------------------------------------------------------------
__global__ void finalize_kernel(float* __restrict__ out, int loss_idx) {
    __shared__ double red[256];
    double s = 0.0;
    for (int i = threadIdx.x; i < B_ * D_; i += 256) s += (double)g_part[i];
    red[threadIdx.x] = s;
    __syncthreads();
    for (int o = 128; o > 0; o >>= 1) {
        if (threadIdx.x < o) red[threadIdx.x] += red[threadIdx.x + o];
        __syncthreads();
    }
    if (threadIdx.x == 0) {
        double mse = red[0] / (double)NELM;
        out[loss_idx] = (float)(1.25 * mse);
    }
}

// ---------------------------------------------------------------------------
extern "C" void kernel_launch(void* const* d_in, const int* in_sizes, int n_in,
                              void* d_out, int out_size) {
    const float* X = (const float*)d_in[0];   // [64,256,32,32] f32 NCHW
    const float* C = (const float*)d_in[1];   // [1024,256] f32
    float* out = (float*)d_out;

    static const int SMEM_BYTES = 196608 + 1024;   // A + 2xB (+ align slack)
    cudaFuncSetAttribute(vq_mma_kernel,
                         cudaFuncAttributeMaxDynamicSharedMemorySize, SMEM_BYTES);

    cn_cbf_kernel<<<K_ / 32, 256>>>(C);                            // launch 1
    a_init_kernel<<<NPIX / 256, 256>>>(X);                         // launch 2
    transpose_kernel<<<dim3(HW_ / 32, D_ / 32, B_), dim3(32, 8)>>>(X); // 3
    vq_mma_kernel<<<NPIX / 128, 512, SMEM_BYTES>>>();              // launch 4
    rescore_kernel<<<1024, 256>>>(C);                              // launch 5
    gather_kernel<<<B_ * D_, 256>>>(X, C, out);                    // launch 6
    if (out_size > NELM) {
        finalize_kernel<<<1, 256>>>(out, out_size - 1);            // launch 7
    }
}

// round 10
// speedup vs baseline: 1.4176x; 1.0844x over previous
#include <cuda_runtime.h>
#include <cuda_bf16.h>
#include <cstdint>

// Problem constants (fixed for this dataset)
#define B_   64
#define D_   256
#define HW_  1024            // 32*32
#define K_   1024            // num embeddings
#define NPIX (B_ * HW_)      // 65536
#define NELM (B_ * D_ * HW_) // 16777216
#define CAND_CAP 1048576
#define EPS_MARGIN 5e-3f
#define STAGE_CAP 2816

// ---------------------------------------------------------------------------
// Scratch (device globals; no cudaMalloc allowed)
// ---------------------------------------------------------------------------
__device__ unsigned long long g_best[NPIX];   // packed (orderable_score<<32)|k
__device__ float g_cn[K_];                    // |c_k|^2 (exact sequential chain)
__device__ float g_A[NPIX];                   // |x_n|^2 (exact sequential chain)
__device__ float g_Xt[NPIX * D_];             // X transposed: [pix][d] fp32
__device__ __nv_bfloat16 g_Xt_bf[NPIX * D_];  // bf16 copy
__device__ __nv_bfloat16 g_Cbf[K_ * D_];      // codebook bf16
__device__ unsigned long long g_cand[CAND_CAP]; // (score_bits<<32)|(pix<<10)|k
__device__ unsigned int g_ncand;

__device__ __forceinline__ unsigned int float_to_ordered(float f) {
    unsigned int u = __float_as_uint(f);
    return (u & 0x80000000u) ? ~u : (u | 0x80000000u);
}
__device__ __forceinline__ float ordered_to_float(unsigned int o) {
    unsigned int u = (o & 0x80000000u) ? (o & 0x7FFFFFFFu) : ~o;
    return __uint_as_float(u);
}

__device__ __forceinline__ uint32_t smem_u32(const void* p) {
    uint32_t a;
    asm("{ .reg .u64 t; cvta.to.shared.u64 t, %1; cvt.u32.u64 %0, t; }"
        : "=r"(a) : "l"(p));
    return a;
}

// cp.async 16B (sm_80+, legal on plain sm_103 target)
__device__ __forceinline__ void cp16(uint32_t saddr, const void* g) {
    asm volatile("cp.async.cg.shared.global [%0], [%1], 16;"
                 :: "r"(saddr), "l"(g) : "memory");
}

// ldmatrix x4 (non-transposed, b16)
__device__ __forceinline__ void ldm_x4(uint32_t* r, uint32_t addr) {
    asm volatile("ldmatrix.sync.aligned.m8n8.x4.shared.b16 {%0,%1,%2,%3}, [%4];"
                 : "=r"(r[0]), "=r"(r[1]), "=r"(r[2]), "=r"(r[3]) : "r"(addr));
}

// bf16 HMMA m16n8k16, f32 accumulate (sm_80+)
__device__ __forceinline__ void mma_bf16(float* c, const uint32_t* a,
                                         uint32_t b0, uint32_t b1) {
    asm volatile(
        "mma.sync.aligned.m16n8k16.row.col.f32.bf16.bf16.f32 "
        "{%0,%1,%2,%3}, {%4,%5,%6,%7}, {%8,%9}, {%0,%1,%2,%3};"
        : "+f"(c[0]), "+f"(c[1]), "+f"(c[2]), "+f"(c[3])
        : "r"(a[0]), "r"(a[1]), "r"(a[2]), "r"(a[3]), "r"(b0), "r"(b1));
}

// ---------------------------------------------------------------------------
// Kernel 1: |c_k|^2 (exact sequential chain) + bf16 convert, coalesced.
// ---------------------------------------------------------------------------
__global__ __launch_bounds__(256)
void cn_cbf_kernel(const float* __restrict__ C) {
    __shared__ float rows[32][257];
    const int tid = threadIdx.x;
    const int kb = blockIdx.x * 32;
    if (blockIdx.x == 0 && tid == 0) g_ncand = 0;

    const float4* C4 = reinterpret_cast<const float4*>(C + (size_t)kb * D_);
    uint2* B2 = reinterpret_cast<uint2*>(g_Cbf + (size_t)kb * D_);
    #pragma unroll
    for (int i = 0; i < 8; i++) {
        int idx = i * 256 + tid;          // float4 index: 0..2047
        int r = idx >> 6, c = idx & 63;   // 64 float4 per row
        float4 v = C4[idx];
        rows[r][c * 4 + 0] = v.x;
        rows[r][c * 4 + 1] = v.y;
        rows[r][c * 4 + 2] = v.z;
        rows[r][c * 4 + 3] = v.w;
        __nv_bfloat162 h01 = __floats2bfloat162_rn(v.x, v.y);
        __nv_bfloat162 h23 = __floats2bfloat162_rn(v.z, v.w);
        uint2 pk;
        pk.x = *reinterpret_cast<unsigned int*>(&h01);
        pk.y = *reinterpret_cast<unsigned int*>(&h23);
        B2[idx] = pk;
    }
    __syncthreads();
    if (tid < 32) {
        float s = 0.f;
        #pragma unroll 8
        for (int d = 0; d < D_; d++) {
            float v = rows[tid][d];
            s = __fadd_rn(s, __fmul_rn(v, v));
        }
        g_cn[kb + tid] = s;
    }
}

// ---------------------------------------------------------------------------
// Kernel 2: |x_p|^2 (exact sequential chain). 256x256, coalesced.
// ---------------------------------------------------------------------------
__global__ __launch_bounds__(256)
void a_kernel(const float* __restrict__ X) {
    const int pix = blockIdx.x * 256 + threadIdx.x;
    const int b = pix >> 10, p = pix & 1023;
    const float* Xb = X + (size_t)b * D_ * HW_ + p;
    float s = 0.f;
    #pragma unroll 8
    for (int d = 0; d < D_; d++) {
        float v = Xb[(size_t)d * HW_];
        s = __fadd_rn(s, __fmul_rn(v, v));
    }
    g_A[pix] = s;
}

// ---------------------------------------------------------------------------
// Kernel 3: transpose X NCHW [b][d][p] -> pixel-major [pix][d], f32+bf16
// ---------------------------------------------------------------------------
__global__ __launch_bounds__(256)
void transpose_kernel(const float* __restrict__ X) {
    __shared__ float t[32][33];
    const int b  = blockIdx.z;
    const int dB = blockIdx.y * 32;
    const int pB = blockIdx.x * 32;
    const int tx = threadIdx.x;       // 0..31
    const int ty = threadIdx.y;       // 0..7

    const float* src = X + ((size_t)b * D_ + dB) * HW_ + pB;
    #pragma unroll
    for (int i = 0; i < 32; i += 8)
        t[ty + i][tx] = src[(size_t)(ty + i) * HW_ + tx];
    __syncthreads();

    const size_t obase = ((size_t)(b * HW_ + pB)) * D_ + dB;
    #pragma unroll
    for (int i = 0; i < 32; i += 8) {
        int row = ty + i;
        float v = t[tx][row];
        g_Xt[obase + (size_t)row * D_ + tx] = v;
        g_Xt_bf[obase + (size_t)row * D_ + tx] = __float2bfloat16(v);
    }
}

// ---------------------------------------------------------------------------
// Kernel 4: persistent-A bf16 HMMA GEMM, 128 pixels x ALL 1024 codes per CTA.
// 512 threads / 16 warps, 32x32 warp tile, 2-stage register fragment pipeline.
// Running per-pixel min + candidate staging; singles write g_best directly
// with FULL score A + (cn - 2dot) so the loss pass can sum g_best scores;
// multis go to g_cand for exact rescoring. g_best init done here.
// ---------------------------------------------------------------------------
__global__ __launch_bounds__(512, 1)
void vq_mma_kernel() {
    extern __shared__ char dsm_raw[];
    __shared__ float s_cn[K_];
    __shared__ float s_A[128];
    __shared__ unsigned int s_min[128];
    __shared__ unsigned int s_pcount[128];
    __shared__ unsigned long long stage[STAGE_CAP];
    __shared__ unsigned int s_cnt;

    const int tid = threadIdx.x, lane = tid & 31, wid = tid >> 5;
    const int pt = blockIdx.x;   // 0..511 pixel tiles (128 pixels each)

    const uint32_t s0 = smem_u32(dsm_raw);
    const uint32_t base = (s0 + 1023) & ~1023u;
    const uint32_t sA = base;
    const uint32_t sB0 = base + 65536, sB1 = base + 131072;

    #pragma unroll
    for (int i = 0; i < 2; i++) s_cn[tid + i * 512] = g_cn[tid + i * 512];
    if (tid < 128) {
        s_min[tid] = 0xFFFFFFFFu;
        s_pcount[tid] = 0u;
        s_A[tid] = g_A[pt * 128 + tid];
        g_best[pt * 128 + tid] = 0xFFFFFFFFFFFFFFFFull;
    }
    if (tid == 0) s_cnt = 0;

    // Stage A (once) + B tile 0
    const __nv_bfloat16* gA = g_Xt_bf + (size_t)pt * 128 * D_;
    #pragma unroll
    for (int i = 0; i < 8; i++) {
        int v = i * 512 + tid;             // 0..4095 16B chunks
        int r = v >> 5, c = v & 31;
        uint32_t off = (uint32_t)(r * 512) + (((uint32_t)c * 16) ^ ((uint32_t)(r & 7) << 4));
        cp16(sA + off, gA + (size_t)v * 8);
        cp16(sB0 + off, g_Cbf + (size_t)v * 8);
    }
    asm volatile("cp.async.commit_group;");

    // Warp tiling: 4 (m) x 4 (n), 32x32 per warp
    const int wm = (wid & 3) * 32;
    const int wn = (wid >> 2) * 32;
    const int a_row = wm + (lane & 15);
    const uint32_t a_swz = (uint32_t)((a_row & 7) << 4);
    const int a_kb = (lane >> 4) * 16;
    const int b_row = wn + ((lane & 7) | ((lane & 16) >> 1));
    const uint32_t b_swz = (uint32_t)((b_row & 7) << 4);
    const int b_kb = ((lane >> 3) & 1) * 16;

    const int r0b = wm + (lane >> 2);          // score row base (mi adds 16)
    const int c0b = wn + (lane & 3) * 2;       // score col base (nt adds 8)

    const uint32_t aAddr0 = sA + (uint32_t)a_row * 512;
    const uint32_t aAddr1 = sA + (uint32_t)(a_row + 16) * 512;

    for (int kt = 0; kt < 8; kt++) {
        const uint32_t sBc = (kt & 1) ? sB1 : sB0;
        const uint32_t sBn = (kt & 1) ? sB0 : sB1;

        asm volatile("cp.async.wait_group 0;" ::: "memory");
        __syncthreads();

        // Prefetch next B tile into the alternate buffer
        if (kt + 1 < 8) {
            const __nv_bfloat16* gBn = g_Cbf + (size_t)(kt + 1) * 128 * D_;
            #pragma unroll
            for (int i = 0; i < 8; i++) {
                int v = i * 512 + tid;
                int r = v >> 5, c = v & 31;
                uint32_t off = (uint32_t)(r * 512) +
                               (((uint32_t)c * 16) ^ ((uint32_t)(r & 7) << 4));
                cp16(sBn + off, gBn + (size_t)v * 8);
            }
            asm volatile("cp.async.commit_group;");
        }

        const uint32_t bAddr0 = sBc + (uint32_t)b_row * 512;
        const uint32_t bAddr1 = sBc + (uint32_t)(b_row + 16) * 512;

        float acc[2][4][4];
        #pragma unroll
        for (int mi = 0; mi < 2; mi++)
            #pragma unroll
            for (int nt = 0; nt < 4; nt++)
                #pragma unroll
                for (int e = 0; e < 4; e++) acc[mi][nt][e] = 0.f;

        // 2-stage register fragment pipeline over ks
        uint32_t afb[2][2][4], bfb[2][2][4];
        {
            uint32_t ka = (uint32_t)a_kb ^ a_swz;
            uint32_t kb = (uint32_t)b_kb ^ b_swz;
            ldm_x4(afb[0][0], aAddr0 + ka);
            ldm_x4(afb[0][1], aAddr1 + ka);
            ldm_x4(bfb[0][0], bAddr0 + kb);
            ldm_x4(bfb[0][1], bAddr1 + kb);
        }
        #pragma unroll
        for (int ks = 0; ks < 16; ks++) {
            const int cur = ks & 1, nxt = cur ^ 1;
            if (ks < 15) {
                uint32_t ka = ((uint32_t)((ks + 1) * 32 + a_kb)) ^ a_swz;
                uint32_t kb = ((uint32_t)((ks + 1) * 32 + b_kb)) ^ b_swz;
                ldm_x4(afb[nxt][0], aAddr0 + ka);
                ldm_x4(afb[nxt][1], aAddr1 + ka);
                ldm_x4(bfb[nxt][0], bAddr0 + kb);
                ldm_x4(bfb[nxt][1], bAddr1 + kb);
            }
            #pragma unroll
            for (int mi = 0; mi < 2; mi++)
                #pragma unroll
                for (int nt = 0; nt < 4; nt++)
                    mma_bf16(acc[mi][nt], afb[cur][mi],
                             bfb[cur][nt >> 1][(nt & 1) * 2],
                             bfb[cur][nt >> 1][(nt & 1) * 2 + 1]);
        }

        // Scores IN PLACE: acc <- cn[k] - 2*acc. Update per-pixel running min.
        #pragma unroll
        for (int mi = 0; mi < 2; mi++) {
            float m0 = 3.4e38f, m1 = 3.4e38f;
            #pragma unroll
            for (int nt = 0; nt < 4; nt++) {
                int c0 = c0b + nt * 8;
                float cn0 = s_cn[kt * 128 + c0], cn1 = s_cn[kt * 128 + c0 + 1];
                acc[mi][nt][0] = fmaf(-2.f, acc[mi][nt][0], cn0);
                acc[mi][nt][1] = fmaf(-2.f, acc[mi][nt][1], cn1);
                acc[mi][nt][2] = fmaf(-2.f, acc[mi][nt][2], cn0);
                acc[mi][nt][3] = fmaf(-2.f, acc[mi][nt][3], cn1);
                m0 = fminf(m0, fminf(acc[mi][nt][0], acc[mi][nt][1]));
                m1 = fminf(m1, fminf(acc[mi][nt][2], acc[mi][nt][3]));
            }
            m0 = fminf(m0, __shfl_xor_sync(0xFFFFFFFFu, m0, 1));
            m0 = fminf(m0, __shfl_xor_sync(0xFFFFFFFFu, m0, 2));
            m1 = fminf(m1, __shfl_xor_sync(0xFFFFFFFFu, m1, 1));
            m1 = fminf(m1, __shfl_xor_sync(0xFFFFFFFFu, m1, 2));
            if ((lane & 3) == 0) {
                atomicMin(&s_min[r0b + mi * 16],     float_to_ordered(m0));
                atomicMin(&s_min[r0b + mi * 16 + 8], float_to_ordered(m1));
            }
        }
        // NO syncthreads: stale (larger) min still yields a candidate superset.

        // Emit candidates vs running min
        const unsigned pixb = (unsigned)(pt * 128);
        #pragma unroll
        for (int mi = 0; mi < 2; mi++) {
            int r0 = r0b + mi * 16;
            float thr0 = ordered_to_float(s_min[r0]) + EPS_MARGIN;
            float thr1 = ordered_to_float(s_min[r0 + 8]) + EPS_MARGIN;
            #pragma unroll
            for (int nt = 0; nt < 4; nt++) {
                int c0 = c0b + nt * 8;
                #pragma unroll
                for (int e = 0; e < 4; e++) {
                    float v = acc[mi][nt][e];
                    float thr = (e < 2) ? thr0 : thr1;
                    if (v <= thr) {
                        unsigned row = (unsigned)(r0 + ((e < 2) ? 0 : 8));
                        unsigned k = (unsigned)(kt * 128 + c0 + (e & 1));
                        unsigned long long entry =
                            ((unsigned long long)__float_as_uint(v) << 32) |
                            ((unsigned long long)(pixb + row) << 10) | k;
                        unsigned slot = atomicAdd(&s_cnt, 1u);
                        if (slot < STAGE_CAP) stage[slot] = entry;
                        else {
                            unsigned gs = atomicAdd(&g_ncand, 1u);
                            if (gs < CAND_CAP) g_cand[gs] = entry;
                        }
                    }
                }
            }
        }
    }
    __syncthreads();

    // Final flush, pass 1: count final-filtered candidates per pixel
    const unsigned total = min(s_cnt, (unsigned)STAGE_CAP);
    const bool oflow = (s_cnt > (unsigned)STAGE_CAP);
    for (unsigned i = tid; i < total; i += 512) {
        unsigned long long e = stage[i];
        float v = __uint_as_float((unsigned)(e >> 32));
        unsigned row = ((unsigned)e >> 10) & 127u;
        if (v <= ordered_to_float(s_min[row]) + EPS_MARGIN)
            atomicAdd(&s_pcount[row], 1u);
    }
    __syncthreads();

    // Pass 2: singles -> direct g_best write with FULL score (A + filter
    // score) so finalize can sum g_best; multis -> g_cand for exact rescore.
    const unsigned rounded = (total + 511u) & ~511u;
    for (unsigned i = tid; i < rounded; i += 512) {
        bool pred = false;
        unsigned long long e = 0;
        if (i < total) {
            e = stage[i];
            float v = __uint_as_float((unsigned)(e >> 32));
            unsigned low = (unsigned)e;
            unsigned row = (low >> 10) & 127u;
            if (v <= ordered_to_float(s_min[row]) + EPS_MARGIN) {
                if (s_pcount[row] == 1u && !oflow) {
                    unsigned pix = low >> 10, k = low & 1023u;
                    float full = __fadd_rn(s_A[row], v);   // A + (cn - 2dot)
                    unsigned long long key =
                        ((unsigned long long)float_to_ordered(full) << 32) |
                        (unsigned long long)k;
                    atomicMin(&g_best[pix], key);
                } else {
                    pred = true;
                }
            }
        }
        unsigned mask = __ballot_sync(0xFFFFFFFFu, pred);
        if (mask) {
            int leader = __ffs(mask) - 1;
            unsigned bidx = 0;
            if (lane == leader) bidx = atomicAdd(&g_ncand, (unsigned)__popc(mask));
            bidx = __shfl_sync(0xFFFFFFFFu, bidx, leader);
            if (pred) {
                unsigned dst = bidx + __popc(mask & ((1u << lane) - 1u));
                if (dst < CAND_CAP) g_cand[dst] = e;
            }
        }
    }
}

// ---------------------------------------------------------------------------
// Kernel 5: exact fp32 rescore of multi-candidate entries (one warp each).
// score = fl(fl(A - 2*dot) + cn)  — the Round-2-validated rounding chain.
// ---------------------------------------------------------------------------
__global__ __launch_bounds__(256)
void rescore_kernel(const float* __restrict__ C) {
    const unsigned int count = min(g_ncand, (unsigned)CAND_CAP);
    const int lane = threadIdx.x & 31;
    const unsigned gw = (blockIdx.x * blockDim.x + threadIdx.x) >> 5;
    const unsigned nw = (gridDim.x * blockDim.x) >> 5;

    for (unsigned i = gw; i < count; i += nw) {
        unsigned long long e = g_cand[i];
        unsigned low = (unsigned)e;
        unsigned pix = low >> 10, k = low & 1023u;

        const float4* xr = reinterpret_cast<const float4*>(g_Xt + (size_t)pix * D_);
        const float4* cr = reinterpret_cast<const float4*>(C + (size_t)k * D_);
        float dot = 0.f;
        #pragma unroll
        for (int t = 0; t < 2; t++) {
            float4 xv = xr[lane * 2 + t];
            float4 cv = cr[lane * 2 + t];
            dot = fmaf(xv.x, cv.x, dot);
            dot = fmaf(xv.y, cv.y, dot);
            dot = fmaf(xv.z, cv.z, dot);
            dot = fmaf(xv.w, cv.w, dot);
        }
        #pragma unroll
        for (int o = 16; o > 0; o >>= 1) dot += __shfl_down_sync(0xFFFFFFFFu, dot, o);
        if (lane == 0) {
            float sc = __fadd_rn(__fadd_rn(g_A[pix], __fmul_rn(-2.0f, dot)), g_cn[k]);
            unsigned long long key =
                ((unsigned long long)float_to_ordered(sc) << 32) | (unsigned long long)k;
            atomicMin(&g_best[pix], key);
        }
    }
}

// ---------------------------------------------------------------------------
// Kernel 6: gather output (NCHW), smem-staged code rows (no X read, no loss).
// ---------------------------------------------------------------------------
__global__ __launch_bounds__(256)
void gather_kernel(const float* __restrict__ C, float* __restrict__ out) {
    __shared__ float rows[32][260];
    __shared__ int s_k[32];
    const int tid = threadIdx.x, lane = tid & 31, wid = tid >> 5;
    const int b  = blockIdx.x >> 5;
    const int pB = (blockIdx.x & 31) * 32;

    if (tid < 32)
        s_k[tid] = (int)(unsigned int)(g_best[b * HW_ + pB + tid] & 1023u);
    __syncthreads();

    const float4* C4 = reinterpret_cast<const float4*>(C);
    #pragma unroll
    for (int i = 0; i < 8; i++) {
        int idx = i * 256 + tid;          // 0..2047
        int r = idx >> 6, c = idx & 63;
        float4 v = C4[s_k[r] * 64 + c];
        *reinterpret_cast<float4*>(&rows[r][c * 4]) = v;
    }
    __syncthreads();

    float* ob = out + (size_t)b * D_ * HW_ + pB;
    #pragma unroll
    for (int it = 0; it < 32; it++) {
        int d = it * 8 + wid;
        ob[(size_t)d * HW_ + lane] = rows[lane][d];
    }
}

// ---------------------------------------------------------------------------
// Kernel 7: loss = 1.25 * sum(per-pixel min scores) / NELM, from g_best.
// ---------------------------------------------------------------------------
__global__ __launch_bounds__(1024)
void finalize_kernel(float* __restrict__ out, int loss_idx) {
    __shared__ double red[1024];
    double s = 0.0;
    for (int i = threadIdx.x; i < NPIX; i += 1024)
        s += (double)ordered_to_float((unsigned)(g_best[i] >> 32));
    red[threadIdx.x] = s;
    __syncthreads();
    for (int o = 512; o > 0; o >>= 1) {
        if (threadIdx.x < o) red[threadIdx.x] += red[threadIdx.x + o];
        __syncthreads();
    }
    if (threadIdx.x == 0)
        out[loss_idx] = (float)(1.25 * red[0] / (double)NELM);
}

// ---------------------------------------------------------------------------
extern "C" void kernel_launch(void* const* d_in, const int* in_sizes, int n_in,
                              void* d_out, int out_size) {
    const float* X = (const float*)d_in[0];   // [64,256,32,32] f32 NCHW
    const float* C = (const float*)d_in[1];   // [1024,256] f32
    float* out = (float*)d_out;

    static const int SMEM_BYTES = 196608 + 1024;   // A + 2xB (+ align slack)
    cudaFuncSetAttribute(vq_mma_kernel,
                         cudaFuncAttributeMaxDynamicSharedMemorySize, SMEM_BYTES);

    cn_cbf_kernel<<<K_ / 32, 256>>>(C);
    a_kernel<<<NPIX / 256, 256>>>(X);
    transpose_kernel<<<dim3(HW_ / 32, D_ / 32, B_), dim3(32, 8)>>>(X);
    vq_mma_kernel<<<NPIX / 128, 512, SMEM_BYTES>>>();
    rescore_kernel<<<1024, 256>>>(C);
    gather_kernel<<<NPIX / 32, 256>>>(C, out);
    if (out_size > NELM) {
        finalize_kernel<<<1, 1024>>>(out, out_size - 1);
    }
}